// round 12
// baseline (speedup 1.0000x reference)
#include <cuda_runtime.h>

#define NN 400000
#define NE 2500000
#define NG 512
#define HD 32
#define INF 7
#define C2 2
#define EPSF 1e-5f
#define NSCAN ((NN + 1023) / 1024)   // 391
#define CHUNK 16
#define AGG_BLOCKS 1184

// ---------------- device scratch (static, no runtime alloc) ----------------
__device__ float  g_t[NN * HD];      // t' = dinv[n] * (features @ W)
__device__ float  g_agg[NN * HD];
__device__ float  g_dinv[NN];
__device__ int    g_hist[NN];
__device__ int    g_colptr[NN];
__device__ int    g_cursor[NN];
__device__ int2   g_epair[NE];       // (src, bitcast w) interleaved
__device__ double g_sum[3][HD];
__device__ double g_sumsq[3][HD];
__device__ int    g_blocksums[512];
__device__ float  g_pool[NG * HD];
__device__ int    g_goff[NG + 1];
__device__ int    g_work[4];         // work-stealing counters (one per agg launch)

// packed f32x2 helpers
__device__ __forceinline__ unsigned long long f32x2_dup(float v) {
    unsigned long long r;
    asm("mov.b64 %0, {%1, %1};" : "=l"(r) : "f"(v));
    return r;
}
__device__ __forceinline__ unsigned long long f32x2_fma(unsigned long long a,
                                                        unsigned long long b,
                                                        unsigned long long c) {
    unsigned long long d;
    asm("fma.rn.f32x2 %0, %1, %2, %3;" : "=l"(d) : "l"(a), "l"(b), "l"(c));
    return d;
}

// ---------------- preprocessing ----------------
__global__ void k_init() {
    int i = blockIdx.x * blockDim.x + threadIdx.x;
    if (i < NN) g_hist[i] = 0;
}

__global__ void k_edge(const int* __restrict__ ei) {
    int e = (blockIdx.x * blockDim.x + threadIdx.x) * 2;
    if (e + 1 < NE) {
        int2 c = *(const int2*)&ei[NE + e];
        atomicAdd(&g_hist[c.x], 1);
        atomicAdd(&g_hist[c.y], 1);
    } else if (e < NE) {
        atomicAdd(&g_hist[ei[NE + e]], 1);
    }
}

__global__ void k_scan1() {
    __shared__ int s[1024];
    int t = threadIdx.x;
    int i = blockIdx.x * 1024 + t;
    int v = (i < NN) ? g_hist[i] : 0;
    s[t] = v;
    __syncthreads();
    for (int off = 1; off < 1024; off <<= 1) {
        int x = 0;
        if (t >= off) x = s[t - off];
        __syncthreads();
        s[t] += x;
        __syncthreads();
    }
    if (i < NN) g_colptr[i] = s[t] - v;
    if (t == 1023) g_blocksums[blockIdx.x] = s[t];
}

__global__ void k_scan2() {
    __shared__ int s[512];
    int t = threadIdx.x;
    // fold small zero-inits here (idle single-block kernel; all uses come later)
    if (t < NG) {
#pragma unroll
        for (int q = 0; q < HD; q++) g_pool[t * HD + q] = 0.0f;
    }
    if (t < 3 * HD) { ((double*)g_sum)[t] = 0.0; ((double*)g_sumsq)[t] = 0.0; }
    if (t < 4) g_work[t] = 0;
    int v = (t < NSCAN) ? g_blocksums[t] : 0;
    s[t] = v;
    __syncthreads();
    for (int off = 1; off < 512; off <<= 1) {
        int x = 0;
        if (t >= off) x = s[t - off];
        __syncthreads();
        s[t] += x;
        __syncthreads();
    }
    if (t < NSCAN) g_blocksums[t] = s[t] - v;
}

__global__ void k_scan3(const int* __restrict__ batch) {
    int i = blockIdx.x * blockDim.x + threadIdx.x;
    if (i >= NN) return;
    int v = g_colptr[i] + g_blocksums[i >> 10];
    g_colptr[i] = v;
    g_cursor[i] = v;
    int b = batch[i];
    int prev = (i == 0) ? -1 : batch[i - 1];
    for (int g = prev + 1; g <= b; g++) g_goff[g] = i;
    if (i == NN - 1)
        for (int g = b + 1; g <= NG; g++) g_goff[g] = NN;
}

__global__ void k_scatter(const int* __restrict__ ei, const float* __restrict__ ea) {
    int e = (blockIdx.x * blockDim.x + threadIdx.x) * 2;
    if (e + 1 < NE) {
        int2   r = *(const int2*)&ei[e];
        int2   c = *(const int2*)&ei[NE + e];
        float2 w = *(const float2*)&ea[e];
        int p0 = atomicAdd(&g_cursor[c.x], 1);
        int p1 = atomicAdd(&g_cursor[c.y], 1);
        g_epair[p0] = make_int2(r.x, __float_as_int(w.x));
        g_epair[p1] = make_int2(r.y, __float_as_int(w.y));
    } else if (e < NE) {
        int pos = atomicAdd(&g_cursor[ei[NE + e]], 1);
        g_epair[pos] = make_int2(ei[e], __float_as_int(ea[e]));
    }
}

// ---------------- fused deg/dinv + layer-0 transform: t' = dinv * (x @ W0) ----------------
__global__ void k_t0deg(const float* __restrict__ x, const float* __restrict__ W0) {
    __shared__ float sW[INF * HD];
    for (int i = threadIdx.x; i < INF * HD; i += blockDim.x) sW[i] = W0[i];
    __syncthreads();
    int n = blockIdx.x * blockDim.x + threadIdx.x;
    if (n >= NN) return;
    int st = g_colptr[n];
    int en = (n + 1 < NN) ? __ldg(&g_colptr[n + 1]) : NE;
    float deg = 1.0f;
    for (int k = st; k < en; k++) deg += __int_as_float(__ldg(&g_epair[k].y));
    float dn = rsqrtf(fmaxf(deg, EPSF));
    g_dinv[n] = dn;

    float xi[INF];
#pragma unroll
    for (int k = 0; k < INF; k++) xi[k] = x[n * INF + k];
#pragma unroll
    for (int jq = 0; jq < HD / 4; jq++) {
        float4 a = make_float4(0.f, 0.f, 0.f, 0.f);
#pragma unroll
        for (int k = 0; k < INF; k++) {
            float4 w = *(const float4*)&sW[k * HD + jq * 4];
            a.x += xi[k] * w.x; a.y += xi[k] * w.y;
            a.z += xi[k] * w.z; a.w += xi[k] * w.w;
        }
        a.x *= dn; a.y *= dn; a.z *= dn; a.w *= dn;
        *(float4*)&g_t[n * HD + jq * 4] = a;
    }
}

// ---------------- aggregation: R9 inner loop + work stealing + 2-wide tail ----------------
// layer >= 0: write g_agg + batch stats.  layer == -1: final layer -> pool directly.
__global__ void k_agg(const float* __restrict__ bias, int layer, int slot,
                      const int* __restrict__ batch) {
    __shared__ double ssum[HD], ssq[HD];
    int doStats = (layer >= 0);
    int doPool = (layer < 0);
    if (doStats) {
        if (threadIdx.x < HD) { ssum[threadIdx.x] = 0.0; ssq[threadIdx.x] = 0.0; }
        __syncthreads();
    }
    int lane = threadIdx.x & 31;
    double ls = 0.0, lq = 0.0;
    float bl = bias ? bias[lane] : 0.0f;
    float psum = 0.f;
    int curb = -1;
    for (;;) {
        int c;
        if (lane == 0) c = atomicAdd(&g_work[slot], 1);
        c = __shfl_sync(0xFFFFFFFFu, c, 0);
        int n0 = c * CHUNK;
        if (n0 >= NN) break;
        int n1 = min(n0 + CHUNK, NN);
        int st = __ldg(&g_colptr[n0]);
        for (int n = n0; n < n1; n++) {
            int en = (n + 1 < NN) ? __ldg(&g_colptr[n + 1]) : NE;
            float dc = __ldg(&g_dinv[n]);
            float acc = __ldg(&g_t[n * HD + lane]);          // self term t'[n]
            int k = st;
            for (; k + 4 <= en; k += 4) {
                int2 p0 = __ldg(&g_epair[k + 0]);
                int2 p1 = __ldg(&g_epair[k + 1]);
                int2 p2 = __ldg(&g_epair[k + 2]);
                int2 p3 = __ldg(&g_epair[k + 3]);
                float v0 = __ldg(&g_t[p0.x * HD + lane]);
                float v1 = __ldg(&g_t[p1.x * HD + lane]);
                float v2 = __ldg(&g_t[p2.x * HD + lane]);
                float v3 = __ldg(&g_t[p3.x * HD + lane]);
                acc += __int_as_float(p0.y) * v0;
                acc += __int_as_float(p1.y) * v1;
                acc += __int_as_float(p2.y) * v2;
                acc += __int_as_float(p3.y) * v3;
            }
            if (k + 2 <= en) {                               // 2-wide tail batch
                int2 p0 = __ldg(&g_epair[k + 0]);
                int2 p1 = __ldg(&g_epair[k + 1]);
                float v0 = __ldg(&g_t[p0.x * HD + lane]);
                float v1 = __ldg(&g_t[p1.x * HD + lane]);
                acc += __int_as_float(p0.y) * v0;
                acc += __int_as_float(p1.y) * v1;
                k += 2;
            }
            if (k < en) {                                    // at most one scalar edge
                int2 p = __ldg(&g_epair[k]);
                acc += __int_as_float(p.y) * __ldg(&g_t[p.x * HD + lane]);
            }
            acc = dc * acc + bl;
            if (doPool) {
                int b = __ldg(&batch[n]);                    // uniform -> broadcast
                if (b != curb) {
                    if (curb >= 0) atomicAdd(&g_pool[curb * HD + lane], psum);
                    psum = 0.f;
                    curb = b;
                }
                psum += acc;
            } else {
                g_agg[n * HD + lane] = acc;
                if (doStats) { ls += acc; lq += (double)acc * (double)acc; }
            }
            st = en;
        }
    }
    if (doPool && curb >= 0) atomicAdd(&g_pool[curb * HD + lane], psum);
    if (doStats) {
        atomicAdd(&ssum[lane], ls);
        atomicAdd(&ssq[lane], lq);
        __syncthreads();
        if (threadIdx.x < HD) {
            atomicAdd(&g_sum[layer][threadIdx.x], ssum[threadIdx.x]);
            atomicAdd(&g_sumsq[layer][threadIdx.x], ssq[threadIdx.x]);
        }
    }
}

// ---------------- fused bn-finalize + bn + relu + transform, f32x2 inner product ----------------
__global__ void k_bnt(const float* __restrict__ W, const float* __restrict__ gvec,
                      const float* __restrict__ bvec, int layer) {
    __shared__ float sW[HD * HD];        // row-major [k][j]; 8B-aligned pairs along j
    __shared__ float ssc[HD], ssh[HD];
    for (int i = threadIdx.x; i < HD * HD; i += blockDim.x) sW[i] = W[i];
    if (threadIdx.x < HD) {
        int j = threadIdx.x;
        double mean = g_sum[layer][j] / (double)NN;
        double var = g_sumsq[layer][j] / (double)NN - mean * mean;
        float rstd = (float)rsqrt(var + (double)EPSF);
        float sc = gvec[j] * rstd;
        ssc[j] = sc;
        ssh[j] = bvec[j] - (float)mean * sc;
    }
    __syncthreads();
    int n = blockIdx.x * blockDim.x + threadIdx.x;
    if (n >= NN) return;
    float dn = __ldg(&g_dinv[n]);
    float y[HD];
#pragma unroll
    for (int kq = 0; kq < HD / 4; kq++) {
        float4 a = *(const float4*)&g_agg[n * HD + kq * 4];
        y[kq * 4 + 0] = fmaxf(a.x * ssc[kq * 4 + 0] + ssh[kq * 4 + 0], 0.f);
        y[kq * 4 + 1] = fmaxf(a.y * ssc[kq * 4 + 1] + ssh[kq * 4 + 1], 0.f);
        y[kq * 4 + 2] = fmaxf(a.z * ssc[kq * 4 + 2] + ssh[kq * 4 + 2], 0.f);
        y[kq * 4 + 3] = fmaxf(a.w * ssc[kq * 4 + 3] + ssh[kq * 4 + 3], 0.f);
    }
    unsigned long long acc2[HD / 2];     // 16 packed f32x2 accumulators = 32 outputs
#pragma unroll
    for (int j = 0; j < HD / 2; j++) acc2[j] = 0ull;
#pragma unroll
    for (int k = 0; k < HD; k++) {
        unsigned long long yk2 = f32x2_dup(y[k]);
        const unsigned long long* wrow = (const unsigned long long*)&sW[k * HD];
#pragma unroll
        for (int j = 0; j < HD / 2; j++)
            acc2[j] = f32x2_fma(yk2, wrow[j], acc2[j]);
    }
#pragma unroll
    for (int jq = 0; jq < HD / 4; jq++) {
        float2 lo = *(float2*)&acc2[jq * 2 + 0];
        float2 hi = *(float2*)&acc2[jq * 2 + 1];
        float4 a = make_float4(lo.x * dn, lo.y * dn, hi.x * dn, hi.y * dn);
        *(float4*)&g_t[n * HD + jq * 4] = a;
    }
}

// ---------------- final MLP, single block, 512 threads (one per graph) ----------------
__global__ void k_mlp(const float* __restrict__ Wm0, const float* __restrict__ gm,
                      const float* __restrict__ bm, const float* __restrict__ Wm1,
                      const float* __restrict__ bm1, float* __restrict__ out) {
    __shared__ float sW0[HD * HD];
    __shared__ float sW1[HD * C2];
    __shared__ double ssum[HD], ssq[HD];
    __shared__ float ssc[HD], ssh[HD];
    int t = threadIdx.x;
    for (int i = t; i < HD * HD; i += blockDim.x) sW0[i] = Wm0[i];
    if (t < HD * C2) sW1[t] = Wm1[t];
    if (t < HD) { ssum[t] = 0.0; ssq[t] = 0.0; }
    __syncthreads();

    float p[HD];
#pragma unroll
    for (int k = 0; k < HD; k++) p[k] = g_pool[t * HD + k];
    float u[HD];
#pragma unroll
    for (int j = 0; j < HD; j++) {
        float a = 0.f;
#pragma unroll
        for (int k = 0; k < HD; k++) a += p[k] * sW0[k * HD + j];
        u[j] = a;
    }
    int lane = t & 31;
#pragma unroll
    for (int j = 0; j < HD; j++) {
        float v = u[j];
        float q = u[j] * u[j];
        for (int off = 16; off > 0; off >>= 1) {
            v += __shfl_down_sync(0xFFFFFFFFu, v, off);
            q += __shfl_down_sync(0xFFFFFFFFu, q, off);
        }
        if (lane == 0) {
            atomicAdd(&ssum[j], (double)v);
            atomicAdd(&ssq[j], (double)q);
        }
    }
    __syncthreads();
    if (t < HD) {
        double mean = ssum[t] / (double)NG;
        double var = ssq[t] / (double)NG - mean * mean;
        float rstd = (float)rsqrt(var + (double)EPSF);
        ssc[t] = gm[t] * rstd;
        ssh[t] = bm[t] - (float)mean * gm[t] * rstd;
    }
    __syncthreads();
    float o0 = bm1[0], o1 = bm1[1];
#pragma unroll
    for (int k = 0; k < HD; k++) {
        float yv = fmaxf(u[k] * ssc[k] + ssh[k], 0.f);
        o0 += yv * sW1[k * 2 + 0];
        o1 += yv * sW1[k * 2 + 1];
    }
    out[t * 2 + 0] = o0;
    out[t * 2 + 1] = o1;
}

// ---------------- launch ----------------
extern "C" void kernel_launch(void* const* d_in, const int* in_sizes, int n_in,
                              void* d_out, int out_size) {
    const float* x     = (const float*)d_in[0];
    const int*   ei    = (const int*)d_in[1];
    const float* ea    = (const float*)d_in[2];
    const int*   batch = (const int*)d_in[3];
    const float* W0    = (const float*)d_in[4];
    const float* W1    = (const float*)d_in[6];   // b0..b2, bm0 cancel in batchnorm
    const float* W2    = (const float*)d_in[8];
    const float* W3    = (const float*)d_in[10];
    const float* b3    = (const float*)d_in[11];
    const float* bn_g  = (const float*)d_in[12];  // [3,32]
    const float* bn_b  = (const float*)d_in[13];
    const float* Wm0   = (const float*)d_in[14];
    const float* bnm_g = (const float*)d_in[16];
    const float* bnm_b = (const float*)d_in[17];
    const float* Wm1   = (const float*)d_in[18];
    const float* bm1   = (const float*)d_in[19];
    float* out = (float*)d_out;

    const int nb  = (NN + 255) / 256;
    const int eb2 = (NE / 2 + 255) / 256;

    k_init<<<nb, 256>>>();
    k_edge<<<eb2, 256>>>(ei);
    k_scan1<<<NSCAN, 1024>>>();
    k_scan2<<<1, 512>>>();
    k_scan3<<<nb, 256>>>(batch);
    k_scatter<<<eb2, 256>>>(ei, ea);

    k_t0deg<<<nb, 256>>>(x, W0);
    k_agg<<<AGG_BLOCKS, 256>>>(nullptr, 0, 0, batch);
    k_bnt<<<nb, 256>>>(W1, bn_g + 0 * HD, bn_b + 0 * HD, 0);
    k_agg<<<AGG_BLOCKS, 256>>>(nullptr, 1, 1, batch);
    k_bnt<<<nb, 256>>>(W2, bn_g + 1 * HD, bn_b + 1 * HD, 1);
    k_agg<<<AGG_BLOCKS, 256>>>(nullptr, 2, 2, batch);
    k_bnt<<<nb, 256>>>(W3, bn_g + 2 * HD, bn_b + 2 * HD, 2);
    k_agg<<<AGG_BLOCKS, 256>>>(b3, -1, 3, batch);   // final layer: fused pooling

    k_mlp<<<1, 512>>>(Wm0, bnm_g, bnm_b, Wm1, bm1, out);
}

// round 13
// speedup vs baseline: 1.0137x; 1.0137x over previous
#include <cuda_runtime.h>

#define NN 400000
#define NE 2500000
#define NG 512
#define HD 32
#define INF 7
#define C2 2
#define EPSF 1e-5f
#define NSCAN ((NN + 1023) / 1024)   // 391
#define CHUNK 16
#define AGG_BLOCKS 1184

// ---------------- device scratch (static, no runtime alloc) ----------------
__device__ float  g_t[NN * HD];      // t' = dinv[n] * (features @ W)
__device__ float  g_agg[NN * HD];
__device__ float  g_dinv[NN];
__device__ int    g_hist[NN];
__device__ int    g_colptr[NN];
__device__ int    g_cursor[NN];
__device__ int2   g_epair[NE];       // (src, bitcast w) interleaved
__device__ double g_sum[3][HD];
__device__ double g_sumsq[3][HD];
__device__ int    g_blocksums[512];
__device__ float  g_pool[NG * HD];
__device__ int    g_goff[NG + 1];
__device__ int    g_work[4];         // work-stealing counters (one per agg launch)

// packed f32x2 helpers
__device__ __forceinline__ unsigned long long f32x2_dup(float v) {
    unsigned long long r;
    asm("mov.b64 %0, {%1, %1};" : "=l"(r) : "f"(v));
    return r;
}
__device__ __forceinline__ unsigned long long f32x2_fma(unsigned long long a,
                                                        unsigned long long b,
                                                        unsigned long long c) {
    unsigned long long d;
    asm("fma.rn.f32x2 %0, %1, %2, %3;" : "=l"(d) : "l"(a), "l"(b), "l"(c));
    return d;
}

// ---------------- preprocessing ----------------
__global__ void k_init() {
    int i = blockIdx.x * blockDim.x + threadIdx.x;
    if (i < NN) g_hist[i] = 0;
    if (i < NG * HD) g_pool[i] = 0.0f;   // coalesced
}

__global__ void k_edge(const int* __restrict__ ei) {
    int e = (blockIdx.x * blockDim.x + threadIdx.x) * 2;
    if (e + 1 < NE) {
        int2 c = *(const int2*)&ei[NE + e];
        atomicAdd(&g_hist[c.x], 1);
        atomicAdd(&g_hist[c.y], 1);
    } else if (e < NE) {
        atomicAdd(&g_hist[ei[NE + e]], 1);
    }
}

__global__ void k_scan1() {
    __shared__ int s[1024];
    int t = threadIdx.x;
    int i = blockIdx.x * 1024 + t;
    int v = (i < NN) ? g_hist[i] : 0;
    s[t] = v;
    __syncthreads();
    for (int off = 1; off < 1024; off <<= 1) {
        int x = 0;
        if (t >= off) x = s[t - off];
        __syncthreads();
        s[t] += x;
        __syncthreads();
    }
    if (i < NN) g_colptr[i] = s[t] - v;
    if (t == 1023) g_blocksums[blockIdx.x] = s[t];
}

__global__ void k_scan2() {
    __shared__ int s[512];
    int t = threadIdx.x;
    // tiny zero-inits (196 scalars; negligible)
    if (t < 3 * HD) { ((double*)g_sum)[t] = 0.0; ((double*)g_sumsq)[t] = 0.0; }
    if (t < 4) g_work[t] = 0;
    int v = (t < NSCAN) ? g_blocksums[t] : 0;
    s[t] = v;
    __syncthreads();
    for (int off = 1; off < 512; off <<= 1) {
        int x = 0;
        if (t >= off) x = s[t - off];
        __syncthreads();
        s[t] += x;
        __syncthreads();
    }
    if (t < NSCAN) g_blocksums[t] = s[t] - v;
}

__global__ void k_scan3(const int* __restrict__ batch) {
    int i = blockIdx.x * blockDim.x + threadIdx.x;
    if (i >= NN) return;
    int v = g_colptr[i] + g_blocksums[i >> 10];
    g_colptr[i] = v;
    g_cursor[i] = v;
    int b = batch[i];
    int prev = (i == 0) ? -1 : batch[i - 1];
    for (int g = prev + 1; g <= b; g++) g_goff[g] = i;
    if (i == NN - 1)
        for (int g = b + 1; g <= NG; g++) g_goff[g] = NN;
}

__global__ void k_scatter(const int* __restrict__ ei, const float* __restrict__ ea) {
    int e = (blockIdx.x * blockDim.x + threadIdx.x) * 2;
    if (e + 1 < NE) {
        int2   r = *(const int2*)&ei[e];
        int2   c = *(const int2*)&ei[NE + e];
        float2 w = *(const float2*)&ea[e];
        int p0 = atomicAdd(&g_cursor[c.x], 1);
        int p1 = atomicAdd(&g_cursor[c.y], 1);
        g_epair[p0] = make_int2(r.x, __float_as_int(w.x));
        g_epair[p1] = make_int2(r.y, __float_as_int(w.y));
    } else if (e < NE) {
        int pos = atomicAdd(&g_cursor[ei[NE + e]], 1);
        g_epair[pos] = make_int2(ei[e], __float_as_int(ea[e]));
    }
}

// ---------------- fused deg/dinv + layer-0 transform: t' = dinv * (x @ W0) ----------------
__global__ void k_t0deg(const float* __restrict__ x, const float* __restrict__ W0) {
    __shared__ float sW[INF * HD];
    for (int i = threadIdx.x; i < INF * HD; i += blockDim.x) sW[i] = W0[i];
    __syncthreads();
    int n = blockIdx.x * blockDim.x + threadIdx.x;
    if (n >= NN) return;
    int st = g_colptr[n];
    int en = (n + 1 < NN) ? __ldg(&g_colptr[n + 1]) : NE;
    float deg = 1.0f;
    for (int k = st; k < en; k++) deg += __int_as_float(__ldg(&g_epair[k].y));
    float dn = rsqrtf(fmaxf(deg, EPSF));
    g_dinv[n] = dn;

    float xi[INF];
#pragma unroll
    for (int k = 0; k < INF; k++) xi[k] = x[n * INF + k];
#pragma unroll
    for (int jq = 0; jq < HD / 4; jq++) {
        float4 a = make_float4(0.f, 0.f, 0.f, 0.f);
#pragma unroll
        for (int k = 0; k < INF; k++) {
            float4 w = *(const float4*)&sW[k * HD + jq * 4];
            a.x += xi[k] * w.x; a.y += xi[k] * w.y;
            a.z += xi[k] * w.z; a.w += xi[k] * w.w;
        }
        a.x *= dn; a.y *= dn; a.z *= dn; a.w *= dn;
        *(float4*)&g_t[n * HD + jq * 4] = a;
    }
}

// ---------------- aggregation: work stealing + 2-wide tail + L2-only gathers ----------------
// layer >= 0: write g_agg + batch stats.  layer == -1: final layer -> pool directly.
__global__ void k_agg(const float* __restrict__ bias, int layer, int slot,
                      const int* __restrict__ batch) {
    __shared__ double ssum[HD], ssq[HD];
    int doStats = (layer >= 0);
    int doPool = (layer < 0);
    if (doStats) {
        if (threadIdx.x < HD) { ssum[threadIdx.x] = 0.0; ssq[threadIdx.x] = 0.0; }
        __syncthreads();
    }
    int lane = threadIdx.x & 31;
    double ls = 0.0, lq = 0.0;
    float bl = bias ? bias[lane] : 0.0f;
    float psum = 0.f;
    int curb = -1;
    for (;;) {
        int c;
        if (lane == 0) c = atomicAdd(&g_work[slot], 1);
        c = __shfl_sync(0xFFFFFFFFu, c, 0);
        int n0 = c * CHUNK;
        if (n0 >= NN) break;
        int n1 = min(n0 + CHUNK, NN);
        int st = __ldg(&g_colptr[n0]);
        for (int n = n0; n < n1; n++) {
            int en = (n + 1 < NN) ? __ldg(&g_colptr[n + 1]) : NE;
            float dc = __ldg(&g_dinv[n]);
            float acc = __ldg(&g_t[n * HD + lane]);          // self term t'[n]
            int k = st;
            for (; k + 4 <= en; k += 4) {
                int2 p0 = __ldg(&g_epair[k + 0]);
                int2 p1 = __ldg(&g_epair[k + 1]);
                int2 p2 = __ldg(&g_epair[k + 2]);
                int2 p3 = __ldg(&g_epair[k + 3]);
                float v0 = __ldcg(&g_t[p0.x * HD + lane]);   // L2-only gathers
                float v1 = __ldcg(&g_t[p1.x * HD + lane]);
                float v2 = __ldcg(&g_t[p2.x * HD + lane]);
                float v3 = __ldcg(&g_t[p3.x * HD + lane]);
                acc += __int_as_float(p0.y) * v0;
                acc += __int_as_float(p1.y) * v1;
                acc += __int_as_float(p2.y) * v2;
                acc += __int_as_float(p3.y) * v3;
            }
            if (k + 2 <= en) {                               // 2-wide tail batch
                int2 p0 = __ldg(&g_epair[k + 0]);
                int2 p1 = __ldg(&g_epair[k + 1]);
                float v0 = __ldcg(&g_t[p0.x * HD + lane]);
                float v1 = __ldcg(&g_t[p1.x * HD + lane]);
                acc += __int_as_float(p0.y) * v0;
                acc += __int_as_float(p1.y) * v1;
                k += 2;
            }
            if (k < en) {                                    // at most one scalar edge
                int2 p = __ldg(&g_epair[k]);
                acc += __int_as_float(p.y) * __ldcg(&g_t[p.x * HD + lane]);
            }
            acc = dc * acc + bl;
            if (doPool) {
                int b = __ldg(&batch[n]);                    // uniform -> broadcast
                if (b != curb) {
                    if (curb >= 0) atomicAdd(&g_pool[curb * HD + lane], psum);
                    psum = 0.f;
                    curb = b;
                }
                psum += acc;
            } else {
                g_agg[n * HD + lane] = acc;
                if (doStats) { ls += acc; lq += (double)acc * (double)acc; }
            }
            st = en;
        }
    }
    if (doPool && curb >= 0) atomicAdd(&g_pool[curb * HD + lane], psum);
    if (doStats) {
        atomicAdd(&ssum[lane], ls);
        atomicAdd(&ssq[lane], lq);
        __syncthreads();
        if (threadIdx.x < HD) {
            atomicAdd(&g_sum[layer][threadIdx.x], ssum[threadIdx.x]);
            atomicAdd(&g_sumsq[layer][threadIdx.x], ssq[threadIdx.x]);
        }
    }
}

// ---------------- fused bn-finalize + bn + relu + transform, f32x2 inner product ----------------
__global__ void k_bnt(const float* __restrict__ W, const float* __restrict__ gvec,
                      const float* __restrict__ bvec, int layer) {
    __shared__ float sW[HD * HD];        // row-major [k][j]; 8B-aligned pairs along j
    __shared__ float ssc[HD], ssh[HD];
    for (int i = threadIdx.x; i < HD * HD; i += blockDim.x) sW[i] = W[i];
    if (threadIdx.x < HD) {
        int j = threadIdx.x;
        double mean = g_sum[layer][j] / (double)NN;
        double var = g_sumsq[layer][j] / (double)NN - mean * mean;
        float rstd = (float)rsqrt(var + (double)EPSF);
        float sc = gvec[j] * rstd;
        ssc[j] = sc;
        ssh[j] = bvec[j] - (float)mean * sc;
    }
    __syncthreads();
    int n = blockIdx.x * blockDim.x + threadIdx.x;
    if (n >= NN) return;
    float dn = __ldg(&g_dinv[n]);
    float y[HD];
#pragma unroll
    for (int kq = 0; kq < HD / 4; kq++) {
        float4 a = *(const float4*)&g_agg[n * HD + kq * 4];
        y[kq * 4 + 0] = fmaxf(a.x * ssc[kq * 4 + 0] + ssh[kq * 4 + 0], 0.f);
        y[kq * 4 + 1] = fmaxf(a.y * ssc[kq * 4 + 1] + ssh[kq * 4 + 1], 0.f);
        y[kq * 4 + 2] = fmaxf(a.z * ssc[kq * 4 + 2] + ssh[kq * 4 + 2], 0.f);
        y[kq * 4 + 3] = fmaxf(a.w * ssc[kq * 4 + 3] + ssh[kq * 4 + 3], 0.f);
    }
    unsigned long long acc2[HD / 2];     // 16 packed f32x2 accumulators = 32 outputs
#pragma unroll
    for (int j = 0; j < HD / 2; j++) acc2[j] = 0ull;
#pragma unroll
    for (int k = 0; k < HD; k++) {
        unsigned long long yk2 = f32x2_dup(y[k]);
        const unsigned long long* wrow = (const unsigned long long*)&sW[k * HD];
#pragma unroll
        for (int j = 0; j < HD / 2; j++)
            acc2[j] = f32x2_fma(yk2, wrow[j], acc2[j]);
    }
#pragma unroll
    for (int jq = 0; jq < HD / 4; jq++) {
        float2 lo = *(float2*)&acc2[jq * 2 + 0];
        float2 hi = *(float2*)&acc2[jq * 2 + 1];
        float4 a = make_float4(lo.x * dn, lo.y * dn, hi.x * dn, hi.y * dn);
        *(float4*)&g_t[n * HD + jq * 4] = a;
    }
}

// ---------------- final MLP, single block, 512 threads (one per graph) ----------------
__global__ void k_mlp(const float* __restrict__ Wm0, const float* __restrict__ gm,
                      const float* __restrict__ bm, const float* __restrict__ Wm1,
                      const float* __restrict__ bm1, float* __restrict__ out) {
    __shared__ float sW0[HD * HD];
    __shared__ float sW1[HD * C2];
    __shared__ double ssum[HD], ssq[HD];
    __shared__ float ssc[HD], ssh[HD];
    int t = threadIdx.x;
    for (int i = t; i < HD * HD; i += blockDim.x) sW0[i] = Wm0[i];
    if (t < HD * C2) sW1[t] = Wm1[t];
    if (t < HD) { ssum[t] = 0.0; ssq[t] = 0.0; }
    __syncthreads();

    float p[HD];
#pragma unroll
    for (int k = 0; k < HD; k++) p[k] = g_pool[t * HD + k];
    float u[HD];
#pragma unroll
    for (int j = 0; j < HD; j++) {
        float a = 0.f;
#pragma unroll
        for (int k = 0; k < HD; k++) a += p[k] * sW0[k * HD + j];
        u[j] = a;
    }
    int lane = t & 31;
#pragma unroll
    for (int j = 0; j < HD; j++) {
        float v = u[j];
        float q = u[j] * u[j];
        for (int off = 16; off > 0; off >>= 1) {
            v += __shfl_down_sync(0xFFFFFFFFu, v, off);
            q += __shfl_down_sync(0xFFFFFFFFu, q, off);
        }
        if (lane == 0) {
            atomicAdd(&ssum[j], (double)v);
            atomicAdd(&ssq[j], (double)q);
        }
    }
    __syncthreads();
    if (t < HD) {
        double mean = ssum[t] / (double)NG;
        double var = ssq[t] / (double)NG - mean * mean;
        float rstd = (float)rsqrt(var + (double)EPSF);
        ssc[t] = gm[t] * rstd;
        ssh[t] = bm[t] - (float)mean * gm[t] * rstd;
    }
    __syncthreads();
    float o0 = bm1[0], o1 = bm1[1];
#pragma unroll
    for (int k = 0; k < HD; k++) {
        float yv = fmaxf(u[k] * ssc[k] + ssh[k], 0.f);
        o0 += yv * sW1[k * 2 + 0];
        o1 += yv * sW1[k * 2 + 1];
    }
    out[t * 2 + 0] = o0;
    out[t * 2 + 1] = o1;
}

// ---------------- launch ----------------
extern "C" void kernel_launch(void* const* d_in, const int* in_sizes, int n_in,
                              void* d_out, int out_size) {
    const float* x     = (const float*)d_in[0];
    const int*   ei    = (const int*)d_in[1];
    const float* ea    = (const float*)d_in[2];
    const int*   batch = (const int*)d_in[3];
    const float* W0    = (const float*)d_in[4];
    const float* W1    = (const float*)d_in[6];   // b0..b2, bm0 cancel in batchnorm
    const float* W2    = (const float*)d_in[8];
    const float* W3    = (const float*)d_in[10];
    const float* b3    = (const float*)d_in[11];
    const float* bn_g  = (const float*)d_in[12];  // [3,32]
    const float* bn_b  = (const float*)d_in[13];
    const float* Wm0   = (const float*)d_in[14];
    const float* bnm_g = (const float*)d_in[16];
    const float* bnm_b = (const float*)d_in[17];
    const float* Wm1   = (const float*)d_in[18];
    const float* bm1   = (const float*)d_in[19];
    float* out = (float*)d_out;

    const int nb  = (NN + 255) / 256;
    const int eb2 = (NE / 2 + 255) / 256;

    k_init<<<nb, 256>>>();
    k_edge<<<eb2, 256>>>(ei);
    k_scan1<<<NSCAN, 1024>>>();
    k_scan2<<<1, 512>>>();
    k_scan3<<<nb, 256>>>(batch);
    k_scatter<<<eb2, 256>>>(ei, ea);

    k_t0deg<<<nb, 256>>>(x, W0);
    k_agg<<<AGG_BLOCKS, 256>>>(nullptr, 0, 0, batch);
    k_bnt<<<nb, 256>>>(W1, bn_g + 0 * HD, bn_b + 0 * HD, 0);
    k_agg<<<AGG_BLOCKS, 256>>>(nullptr, 1, 1, batch);
    k_bnt<<<nb, 256>>>(W2, bn_g + 1 * HD, bn_b + 1 * HD, 1);
    k_agg<<<AGG_BLOCKS, 256>>>(nullptr, 2, 2, batch);
    k_bnt<<<nb, 256>>>(W3, bn_g + 2 * HD, bn_b + 2 * HD, 2);
    k_agg<<<AGG_BLOCKS, 256>>>(b3, -1, 3, batch);   // final layer: fused pooling

    k_mlp<<<1, 512>>>(Wm0, bnm_g, bnm_b, Wm1, bm1, out);
}

// round 14
// speedup vs baseline: 1.0227x; 1.0088x over previous
#include <cuda_runtime.h>

#define NN 400000
#define NE 2500000
#define NG 512
#define HD 32
#define INF 7
#define C2 2
#define EPSF 1e-5f
#define NSCAN ((NN + 1023) / 1024)   // 391
#define CHUNK 8
#define AGG_BLOCKS 1184

// ---------------- device scratch (static, no runtime alloc) ----------------
__device__ float  g_t[NN * HD];      // t' = dinv[n] * (features @ W)
__device__ float  g_agg[NN * HD];
__device__ float  g_dinv[NN];
__device__ int    g_hist[NN];
__device__ int    g_colptr[NN];
__device__ int    g_cursor[NN];
__device__ int2   g_epair[NE];       // (src, bitcast w) interleaved
__device__ double g_sum[3][HD];
__device__ double g_sumsq[3][HD];
__device__ int    g_blocksums[512];
__device__ float  g_pool[NG * HD];
__device__ int    g_goff[NG + 1];
__device__ int    g_work[4];         // work-stealing counters (one per agg launch)

// packed f32x2 helpers
__device__ __forceinline__ unsigned long long f32x2_dup(float v) {
    unsigned long long r;
    asm("mov.b64 %0, {%1, %1};" : "=l"(r) : "f"(v));
    return r;
}
__device__ __forceinline__ unsigned long long f32x2_fma(unsigned long long a,
                                                        unsigned long long b,
                                                        unsigned long long c) {
    unsigned long long d;
    asm("fma.rn.f32x2 %0, %1, %2, %3;" : "=l"(d) : "l"(a), "l"(b), "l"(c));
    return d;
}

// ---------------- preprocessing ----------------
__global__ void k_init() {
    int i = blockIdx.x * blockDim.x + threadIdx.x;
    if (i < NN) g_hist[i] = 0;
    if (i < NG * HD) g_pool[i] = 0.0f;   // coalesced
}

__global__ void k_edge(const int* __restrict__ ei) {
    int e = (blockIdx.x * blockDim.x + threadIdx.x) * 4;
    if (e + 3 < NE) {
        int4 c = *(const int4*)&ei[NE + e];
        atomicAdd(&g_hist[c.x], 1);
        atomicAdd(&g_hist[c.y], 1);
        atomicAdd(&g_hist[c.z], 1);
        atomicAdd(&g_hist[c.w], 1);
    } else {
        for (; e < NE; e++) atomicAdd(&g_hist[ei[NE + e]], 1);
    }
}

__global__ void k_scan1() {
    __shared__ int s[1024];
    int t = threadIdx.x;
    int i = blockIdx.x * 1024 + t;
    int v = (i < NN) ? g_hist[i] : 0;
    s[t] = v;
    __syncthreads();
    for (int off = 1; off < 1024; off <<= 1) {
        int x = 0;
        if (t >= off) x = s[t - off];
        __syncthreads();
        s[t] += x;
        __syncthreads();
    }
    if (i < NN) g_colptr[i] = s[t] - v;
    if (t == 1023) g_blocksums[blockIdx.x] = s[t];
}

__global__ void k_scan2() {
    __shared__ int s[512];
    int t = threadIdx.x;
    // tiny zero-inits (196 scalars; negligible)
    if (t < 3 * HD) { ((double*)g_sum)[t] = 0.0; ((double*)g_sumsq)[t] = 0.0; }
    if (t < 4) g_work[t] = 0;
    int v = (t < NSCAN) ? g_blocksums[t] : 0;
    s[t] = v;
    __syncthreads();
    for (int off = 1; off < 512; off <<= 1) {
        int x = 0;
        if (t >= off) x = s[t - off];
        __syncthreads();
        s[t] += x;
        __syncthreads();
    }
    if (t < NSCAN) g_blocksums[t] = s[t] - v;
}

__global__ void k_scan3(const int* __restrict__ batch) {
    int i = blockIdx.x * blockDim.x + threadIdx.x;
    if (i >= NN) return;
    int v = g_colptr[i] + g_blocksums[i >> 10];
    g_colptr[i] = v;
    g_cursor[i] = v;
    int b = batch[i];
    int prev = (i == 0) ? -1 : batch[i - 1];
    for (int g = prev + 1; g <= b; g++) g_goff[g] = i;
    if (i == NN - 1)
        for (int g = b + 1; g <= NG; g++) g_goff[g] = NN;
}

__global__ void k_scatter(const int* __restrict__ ei, const float* __restrict__ ea) {
    int e = (blockIdx.x * blockDim.x + threadIdx.x) * 4;
    if (e + 3 < NE) {
        int4   r = *(const int4*)&ei[e];
        int4   c = *(const int4*)&ei[NE + e];
        float4 w = *(const float4*)&ea[e];
        int p0 = atomicAdd(&g_cursor[c.x], 1);
        int p1 = atomicAdd(&g_cursor[c.y], 1);
        int p2 = atomicAdd(&g_cursor[c.z], 1);
        int p3 = atomicAdd(&g_cursor[c.w], 1);
        g_epair[p0] = make_int2(r.x, __float_as_int(w.x));
        g_epair[p1] = make_int2(r.y, __float_as_int(w.y));
        g_epair[p2] = make_int2(r.z, __float_as_int(w.z));
        g_epair[p3] = make_int2(r.w, __float_as_int(w.w));
    } else {
        for (; e < NE; e++) {
            int pos = atomicAdd(&g_cursor[ei[NE + e]], 1);
            g_epair[pos] = make_int2(ei[e], __float_as_int(ea[e]));
        }
    }
}

// ---------------- fused deg/dinv + layer-0 transform: t' = dinv * (x @ W0) ----------------
__global__ void k_t0deg(const float* __restrict__ x, const float* __restrict__ W0) {
    __shared__ float sW[INF * HD];
    for (int i = threadIdx.x; i < INF * HD; i += blockDim.x) sW[i] = W0[i];
    __syncthreads();
    int n = blockIdx.x * blockDim.x + threadIdx.x;
    if (n >= NN) return;
    int st = g_colptr[n];
    int en = (n + 1 < NN) ? __ldg(&g_colptr[n + 1]) : NE;
    float deg = 1.0f;
    for (int k = st; k < en; k++) deg += __int_as_float(__ldg(&g_epair[k].y));
    float dn = rsqrtf(fmaxf(deg, EPSF));
    g_dinv[n] = dn;

    float xi[INF];
#pragma unroll
    for (int k = 0; k < INF; k++) xi[k] = x[n * INF + k];
#pragma unroll
    for (int jq = 0; jq < HD / 4; jq++) {
        float4 a = make_float4(0.f, 0.f, 0.f, 0.f);
#pragma unroll
        for (int k = 0; k < INF; k++) {
            float4 w = *(const float4*)&sW[k * HD + jq * 4];
            a.x += xi[k] * w.x; a.y += xi[k] * w.y;
            a.z += xi[k] * w.z; a.w += xi[k] * w.w;
        }
        a.x *= dn; a.y *= dn; a.z *= dn; a.w *= dn;
        *(float4*)&g_t[n * HD + jq * 4] = a;
    }
}

// ---------------- aggregation: work stealing + 2-wide tail + L2-only gathers ----------------
// layer >= 0: write g_agg + batch stats.  layer == -1: final layer -> pool directly.
__global__ void k_agg(const float* __restrict__ bias, int layer, int slot,
                      const int* __restrict__ batch) {
    __shared__ double ssum[HD], ssq[HD];
    int doStats = (layer >= 0);
    int doPool = (layer < 0);
    if (doStats) {
        if (threadIdx.x < HD) { ssum[threadIdx.x] = 0.0; ssq[threadIdx.x] = 0.0; }
        __syncthreads();
    }
    int lane = threadIdx.x & 31;
    double ls = 0.0, lq = 0.0;
    float bl = bias ? bias[lane] : 0.0f;
    float psum = 0.f;
    int curb = -1;
    for (;;) {
        int c;
        if (lane == 0) c = atomicAdd(&g_work[slot], 1);
        c = __shfl_sync(0xFFFFFFFFu, c, 0);
        int n0 = c * CHUNK;
        if (n0 >= NN) break;
        int n1 = min(n0 + CHUNK, NN);
        int st = __ldg(&g_colptr[n0]);
        for (int n = n0; n < n1; n++) {
            int en = (n + 1 < NN) ? __ldg(&g_colptr[n + 1]) : NE;
            float dc = __ldg(&g_dinv[n]);
            float acc = __ldg(&g_t[n * HD + lane]);          // self term t'[n]
            int k = st;
            for (; k + 4 <= en; k += 4) {
                int2 p0 = __ldg(&g_epair[k + 0]);
                int2 p1 = __ldg(&g_epair[k + 1]);
                int2 p2 = __ldg(&g_epair[k + 2]);
                int2 p3 = __ldg(&g_epair[k + 3]);
                float v0 = __ldcg(&g_t[p0.x * HD + lane]);   // L2-only gathers
                float v1 = __ldcg(&g_t[p1.x * HD + lane]);
                float v2 = __ldcg(&g_t[p2.x * HD + lane]);
                float v3 = __ldcg(&g_t[p3.x * HD + lane]);
                acc += __int_as_float(p0.y) * v0;
                acc += __int_as_float(p1.y) * v1;
                acc += __int_as_float(p2.y) * v2;
                acc += __int_as_float(p3.y) * v3;
            }
            if (k + 2 <= en) {                               // 2-wide tail batch
                int2 p0 = __ldg(&g_epair[k + 0]);
                int2 p1 = __ldg(&g_epair[k + 1]);
                float v0 = __ldcg(&g_t[p0.x * HD + lane]);
                float v1 = __ldcg(&g_t[p1.x * HD + lane]);
                acc += __int_as_float(p0.y) * v0;
                acc += __int_as_float(p1.y) * v1;
                k += 2;
            }
            if (k < en) {                                    // at most one scalar edge
                int2 p = __ldg(&g_epair[k]);
                acc += __int_as_float(p.y) * __ldcg(&g_t[p.x * HD + lane]);
            }
            acc = dc * acc + bl;
            if (doPool) {
                int b = __ldg(&batch[n]);                    // uniform -> broadcast
                if (b != curb) {
                    if (curb >= 0) atomicAdd(&g_pool[curb * HD + lane], psum);
                    psum = 0.f;
                    curb = b;
                }
                psum += acc;
            } else {
                g_agg[n * HD + lane] = acc;
                if (doStats) { ls += acc; lq += (double)acc * (double)acc; }
            }
            st = en;
        }
    }
    if (doPool && curb >= 0) atomicAdd(&g_pool[curb * HD + lane], psum);
    if (doStats) {
        atomicAdd(&ssum[lane], ls);
        atomicAdd(&ssq[lane], lq);
        __syncthreads();
        if (threadIdx.x < HD) {
            atomicAdd(&g_sum[layer][threadIdx.x], ssum[threadIdx.x]);
            atomicAdd(&g_sumsq[layer][threadIdx.x], ssq[threadIdx.x]);
        }
    }
}

// ---------------- fused bn-finalize + bn + relu + transform, f32x2 inner product ----------------
__global__ void k_bnt(const float* __restrict__ W, const float* __restrict__ gvec,
                      const float* __restrict__ bvec, int layer) {
    __shared__ float sW[HD * HD];        // row-major [k][j]; 8B-aligned pairs along j
    __shared__ float ssc[HD], ssh[HD];
    for (int i = threadIdx.x; i < HD * HD; i += blockDim.x) sW[i] = W[i];
    if (threadIdx.x < HD) {
        int j = threadIdx.x;
        double mean = g_sum[layer][j] / (double)NN;
        double var = g_sumsq[layer][j] / (double)NN - mean * mean;
        float rstd = (float)rsqrt(var + (double)EPSF);
        float sc = gvec[j] * rstd;
        ssc[j] = sc;
        ssh[j] = bvec[j] - (float)mean * sc;
    }
    __syncthreads();
    int n = blockIdx.x * blockDim.x + threadIdx.x;
    if (n >= NN) return;
    float dn = __ldg(&g_dinv[n]);
    float y[HD];
#pragma unroll
    for (int kq = 0; kq < HD / 4; kq++) {
        float4 a = *(const float4*)&g_agg[n * HD + kq * 4];
        y[kq * 4 + 0] = fmaxf(a.x * ssc[kq * 4 + 0] + ssh[kq * 4 + 0], 0.f);
        y[kq * 4 + 1] = fmaxf(a.y * ssc[kq * 4 + 1] + ssh[kq * 4 + 1], 0.f);
        y[kq * 4 + 2] = fmaxf(a.z * ssc[kq * 4 + 2] + ssh[kq * 4 + 2], 0.f);
        y[kq * 4 + 3] = fmaxf(a.w * ssc[kq * 4 + 3] + ssh[kq * 4 + 3], 0.f);
    }
    unsigned long long acc2[HD / 2];     // 16 packed f32x2 accumulators = 32 outputs
#pragma unroll
    for (int j = 0; j < HD / 2; j++) acc2[j] = 0ull;
#pragma unroll
    for (int k = 0; k < HD; k++) {
        unsigned long long yk2 = f32x2_dup(y[k]);
        const unsigned long long* wrow = (const unsigned long long*)&sW[k * HD];
#pragma unroll
        for (int j = 0; j < HD / 2; j++)
            acc2[j] = f32x2_fma(yk2, wrow[j], acc2[j]);
    }
#pragma unroll
    for (int jq = 0; jq < HD / 4; jq++) {
        float2 lo = *(float2*)&acc2[jq * 2 + 0];
        float2 hi = *(float2*)&acc2[jq * 2 + 1];
        float4 a = make_float4(lo.x * dn, lo.y * dn, hi.x * dn, hi.y * dn);
        *(float4*)&g_t[n * HD + jq * 4] = a;
    }
}

// ---------------- final MLP, single block, 512 threads (one per graph) ----------------
__global__ void k_mlp(const float* __restrict__ Wm0, const float* __restrict__ gm,
                      const float* __restrict__ bm, const float* __restrict__ Wm1,
                      const float* __restrict__ bm1, float* __restrict__ out) {
    __shared__ float sW0[HD * HD];
    __shared__ float sW1[HD * C2];
    __shared__ double ssum[HD], ssq[HD];
    __shared__ float ssc[HD], ssh[HD];
    int t = threadIdx.x;
    for (int i = t; i < HD * HD; i += blockDim.x) sW0[i] = Wm0[i];
    if (t < HD * C2) sW1[t] = Wm1[t];
    if (t < HD) { ssum[t] = 0.0; ssq[t] = 0.0; }
    __syncthreads();

    float p[HD];
#pragma unroll
    for (int k = 0; k < HD; k++) p[k] = g_pool[t * HD + k];
    float u[HD];
#pragma unroll
    for (int j = 0; j < HD; j++) {
        float a = 0.f;
#pragma unroll
        for (int k = 0; k < HD; k++) a += p[k] * sW0[k * HD + j];
        u[j] = a;
    }
    int lane = t & 31;
#pragma unroll
    for (int j = 0; j < HD; j++) {
        float v = u[j];
        float q = u[j] * u[j];
        for (int off = 16; off > 0; off >>= 1) {
            v += __shfl_down_sync(0xFFFFFFFFu, v, off);
            q += __shfl_down_sync(0xFFFFFFFFu, q, off);
        }
        if (lane == 0) {
            atomicAdd(&ssum[j], (double)v);
            atomicAdd(&ssq[j], (double)q);
        }
    }
    __syncthreads();
    if (t < HD) {
        double mean = ssum[t] / (double)NG;
        double var = ssq[t] / (double)NG - mean * mean;
        float rstd = (float)rsqrt(var + (double)EPSF);
        ssc[t] = gm[t] * rstd;
        ssh[t] = bm[t] - (float)mean * gm[t] * rstd;
    }
    __syncthreads();
    float o0 = bm1[0], o1 = bm1[1];
#pragma unroll
    for (int k = 0; k < HD; k++) {
        float yv = fmaxf(u[k] * ssc[k] + ssh[k], 0.f);
        o0 += yv * sW1[k * 2 + 0];
        o1 += yv * sW1[k * 2 + 1];
    }
    out[t * 2 + 0] = o0;
    out[t * 2 + 1] = o1;
}

// ---------------- launch ----------------
extern "C" void kernel_launch(void* const* d_in, const int* in_sizes, int n_in,
                              void* d_out, int out_size) {
    const float* x     = (const float*)d_in[0];
    const int*   ei    = (const int*)d_in[1];
    const float* ea    = (const float*)d_in[2];
    const int*   batch = (const int*)d_in[3];
    const float* W0    = (const float*)d_in[4];
    const float* W1    = (const float*)d_in[6];   // b0..b2, bm0 cancel in batchnorm
    const float* W2    = (const float*)d_in[8];
    const float* W3    = (const float*)d_in[10];
    const float* b3    = (const float*)d_in[11];
    const float* bn_g  = (const float*)d_in[12];  // [3,32]
    const float* bn_b  = (const float*)d_in[13];
    const float* Wm0   = (const float*)d_in[14];
    const float* bnm_g = (const float*)d_in[16];
    const float* bnm_b = (const float*)d_in[17];
    const float* Wm1   = (const float*)d_in[18];
    const float* bm1   = (const float*)d_in[19];
    float* out = (float*)d_out;

    const int nb  = (NN + 255) / 256;
    const int eb4 = (NE / 4 + 255) / 256;

    k_init<<<nb, 256>>>();
    k_edge<<<eb4, 256>>>(ei);
    k_scan1<<<NSCAN, 1024>>>();
    k_scan2<<<1, 512>>>();
    k_scan3<<<nb, 256>>>(batch);
    k_scatter<<<eb4, 256>>>(ei, ea);

    k_t0deg<<<nb, 256>>>(x, W0);
    k_agg<<<AGG_BLOCKS, 256>>>(nullptr, 0, 0, batch);
    k_bnt<<<nb, 256>>>(W1, bn_g + 0 * HD, bn_b + 0 * HD, 0);
    k_agg<<<AGG_BLOCKS, 256>>>(nullptr, 1, 1, batch);
    k_bnt<<<nb, 256>>>(W2, bn_g + 1 * HD, bn_b + 1 * HD, 1);
    k_agg<<<AGG_BLOCKS, 256>>>(nullptr, 2, 2, batch);
    k_bnt<<<nb, 256>>>(W3, bn_g + 2 * HD, bn_b + 2 * HD, 2);
    k_agg<<<AGG_BLOCKS, 256>>>(b3, -1, 3, batch);   // final layer: fused pooling

    k_mlp<<<1, 512>>>(Wm0, bnm_g, bnm_b, Wm1, bm1, out);
}